// round 5
// baseline (speedup 1.0000x reference)
#include <cuda_runtime.h>
#include <cstdint>
#include <float.h>

// Problem shape (fixed by the reference)
#define NS   16384   // samples
#define DIN  512     // input dim
#define NF   256     // feature dim
#define NC   1000    // classes

// Scratch for feats = x @ W (allocation-free: device global)
__device__ float g_F[NS * NF];

// ---------------- f32x2 packed-FMA helpers (Blackwell) ----------------
__device__ __forceinline__ void ffma2(unsigned long long& acc,
                                      unsigned long long a,
                                      unsigned long long b) {
    asm("fma.rn.f32x2 %0, %1, %2, %0;" : "+l"(acc) : "l"(a), "l"(b));
}
__device__ __forceinline__ unsigned long long pack2(float x) {
    unsigned long long r;
    asm("mov.b64 %0, {%1, %1};" : "=l"(r) : "f"(x));
    return r;
}
__device__ __forceinline__ float2 unpack2(unsigned long long v) {
    float2 f;
    asm("mov.b64 {%0, %1}, %2;" : "=f"(f.x), "=f"(f.y) : "l"(v));
    return f;
}

// =====================================================================
// Kernel 1: F[NS,NF] = x[NS,DIN] @ W[DIN,NF]   (fp32, f32x2 FMA)
// Tile: 128 rows x 64 cols, BK=16, 256 threads, 8x4 per thread
// A tile stored k-major (transposed) so 8-row a-frags come from LDS.128
// and naturally form f32x2 row-pairs.
// =====================================================================
__global__ __launch_bounds__(256) void k_gemm_xw(const float* __restrict__ x,
                                                 const float* __restrict__ W) {
    __shared__ __align__(16) float As[16][132];  // [k][m], pad 132 for STS conflicts
    __shared__ __align__(16) float Bs[16][64];   // [k][n]

    const int t  = threadIdx.x;
    const int tx = t & 15, ty = t >> 4;
    const int m0 = blockIdx.y * 128;
    const int n0 = blockIdx.x * 64;
    const int row0 = ty * 8, col0 = tx * 4;

    unsigned long long acc[4][4];
#pragma unroll
    for (int p = 0; p < 4; p++)
#pragma unroll
        for (int c = 0; c < 4; c++) acc[p][c] = 0ull;

    for (int k0 = 0; k0 < DIN; k0 += 16) {
        __syncthreads();
        // Load x tile -> As (transpose on store). 512 float4s, 2 per thread.
#pragma unroll
        for (int i = 0; i < 2; i++) {
            int f = t + i * 256;
            int row = f >> 2, kq = f & 3;
            float4 v = *reinterpret_cast<const float4*>(
                &x[(size_t)(m0 + row) * DIN + k0 + kq * 4]);
            As[kq * 4 + 0][row] = v.x;
            As[kq * 4 + 1][row] = v.y;
            As[kq * 4 + 2][row] = v.z;
            As[kq * 4 + 3][row] = v.w;
        }
        // Load W tile -> Bs (no transpose). 1 float4 per thread.
        {
            int kk = t >> 4, nq = t & 15;
            *reinterpret_cast<float4*>(&Bs[kk][nq * 4]) =
                *reinterpret_cast<const float4*>(&W[(size_t)(k0 + kk) * NF + n0 + nq * 4]);
        }
        __syncthreads();

#pragma unroll
        for (int k = 0; k < 16; k++) {
            ulonglong2 a01 = *reinterpret_cast<const ulonglong2*>(&As[k][row0]);
            ulonglong2 a23 = *reinterpret_cast<const ulonglong2*>(&As[k][row0 + 4]);
            float4 bv = *reinterpret_cast<const float4*>(&Bs[k][col0]);
            unsigned long long ap[4] = {a01.x, a01.y, a23.x, a23.y};
            unsigned long long bb[4] = {pack2(bv.x), pack2(bv.y), pack2(bv.z), pack2(bv.w)};
#pragma unroll
            for (int p = 0; p < 4; p++)
#pragma unroll
                for (int c = 0; c < 4; c++) ffma2(acc[p][c], ap[p], bb[c]);
        }
    }

    // Epilogue: unpack row-pairs, store 4-float rows to g_F
#pragma unroll
    for (int p = 0; p < 4; p++) {
        float2 c0 = unpack2(acc[p][0]);
        float2 c1 = unpack2(acc[p][1]);
        float2 c2 = unpack2(acc[p][2]);
        float2 c3 = unpack2(acc[p][3]);
        *reinterpret_cast<float4*>(&g_F[(size_t)(m0 + row0 + 2 * p) * NF + n0 + col0]) =
            make_float4(c0.x, c1.x, c2.x, c3.x);
        *reinterpret_cast<float4*>(&g_F[(size_t)(m0 + row0 + 2 * p + 1) * NF + n0 + col0]) =
            make_float4(c0.y, c1.y, c2.y, c3.y);
    }
}

// =====================================================================
// Kernel 2: S = F @ means^T, per-row argmax (first-max tie-break),
//           one-hot write. 128 rows/CTA, loop 16 class-tiles of 64,
//           K=256 in chunks of 16. Same f32x2 micro-kernel.
// =====================================================================
__global__ __launch_bounds__(256) void k_score_argmax(const float* __restrict__ means,
                                                      float* __restrict__ out) {
    __shared__ __align__(16) float As[16][132];  // [k][m] from g_F
    __shared__ __align__(16) float Bs[16][68];   // [k][class] (transposed means)
    __shared__ int sidx[128];

    const int t  = threadIdx.x;
    const int tx = t & 15, ty = t >> 4;
    const int m0 = blockIdx.x * 128;
    const int row0 = ty * 8, col0 = tx * 4;

    float bvrun[8];
    int   birun[8];
#pragma unroll
    for (int r = 0; r < 8; r++) { bvrun[r] = -FLT_MAX; birun[r] = 0x7FFFFFFF; }

    for (int ct = 0; ct < 16; ct++) {
        const int c0 = ct * 64;
        unsigned long long acc[4][4];
#pragma unroll
        for (int p = 0; p < 4; p++)
#pragma unroll
            for (int c = 0; c < 4; c++) acc[p][c] = 0ull;

        for (int k0 = 0; k0 < NF; k0 += 16) {
            __syncthreads();
            // F tile -> As (transpose on store)
#pragma unroll
            for (int i = 0; i < 2; i++) {
                int f = t + i * 256;
                int row = f >> 2, kq = f & 3;
                float4 v = *reinterpret_cast<const float4*>(
                    &g_F[(size_t)(m0 + row) * NF + k0 + kq * 4]);
                As[kq * 4 + 0][row] = v.x;
                As[kq * 4 + 1][row] = v.y;
                As[kq * 4 + 2][row] = v.z;
                As[kq * 4 + 3][row] = v.w;
            }
            // means tile -> Bs (transpose, zero-pad classes >= NC)
            {
                int c = t >> 2, kq = t & 3;
                int cls = c0 + c;
                float4 v = make_float4(0.f, 0.f, 0.f, 0.f);
                if (cls < NC)
                    v = *reinterpret_cast<const float4*>(&means[(size_t)cls * NF + k0 + kq * 4]);
                Bs[kq * 4 + 0][c] = v.x;
                Bs[kq * 4 + 1][c] = v.y;
                Bs[kq * 4 + 2][c] = v.z;
                Bs[kq * 4 + 3][c] = v.w;
            }
            __syncthreads();

#pragma unroll
            for (int k = 0; k < 16; k++) {
                ulonglong2 a01 = *reinterpret_cast<const ulonglong2*>(&As[k][row0]);
                ulonglong2 a23 = *reinterpret_cast<const ulonglong2*>(&As[k][row0 + 4]);
                float4 bv = *reinterpret_cast<const float4*>(&Bs[k][col0]);
                unsigned long long ap[4] = {a01.x, a01.y, a23.x, a23.y};
                unsigned long long bb[4] = {pack2(bv.x), pack2(bv.y), pack2(bv.z), pack2(bv.w)};
#pragma unroll
                for (int p = 0; p < 4; p++)
#pragma unroll
                    for (int c = 0; c < 4; c++) ffma2(acc[p][c], ap[p], bb[c]);
            }
        }

        // Reduce this 64-class tile into the running per-row best.
#pragma unroll
        for (int p = 0; p < 4; p++) {
            float2 u0 = unpack2(acc[p][0]);
            float2 u1 = unpack2(acc[p][1]);
            float2 u2 = unpack2(acc[p][2]);
            float2 u3 = unpack2(acc[p][3]);
            float srow[2][4] = {{u0.x, u1.x, u2.x, u3.x},   // row 2p
                                {u0.y, u1.y, u2.y, u3.y}};  // row 2p+1
#pragma unroll
            for (int h = 0; h < 2; h++) {
                float v = -FLT_MAX;
                int idx = 0x7FFFFFFF;
#pragma unroll
                for (int j = 0; j < 4; j++) {
                    int cls = c0 + col0 + j;
                    // ascending j: strict > keeps lowest class on ties
                    if (cls < NC && srow[h][j] > v) { v = srow[h][j]; idx = cls; }
                }
                // Butterfly across the 16-lane (tx) group; xor<=8 stays in-half.
#pragma unroll
                for (int off = 1; off < 16; off <<= 1) {
                    float ov = __shfl_xor_sync(0xffffffffu, v, off);
                    int   oi = __shfl_xor_sync(0xffffffffu, idx, off);
                    if (ov > v || (ov == v && oi < idx)) { v = ov; idx = oi; }
                }
                int r = 2 * p + h;
                // later tiles have strictly larger class ids: strict > keeps first max
                if (v > bvrun[r] || (v == bvrun[r] && idx < birun[r])) {
                    bvrun[r] = v;
                    birun[r] = idx;
                }
            }
        }
    }

    if (tx == 0) {
#pragma unroll
        for (int r = 0; r < 8; r++) sidx[row0 + r] = birun[r];
    }
    __syncthreads();

    // One-hot write: zero-fill (coalesced float4, 250 lanes cover a 1000-float row)
    const float4 z4 = make_float4(0.f, 0.f, 0.f, 0.f);
    for (int r = 0; r < 128; r++) {
        if (t < 250)
            reinterpret_cast<float4*>(&out[(size_t)(m0 + r) * NC])[t] = z4;
    }
    __syncthreads();
    if (t < 128) out[(size_t)(m0 + t) * NC + sidx[t]] = 1.0f;
}

// =====================================================================
extern "C" void kernel_launch(void* const* d_in, const int* in_sizes, int n_in,
                              void* d_out, int out_size) {
    const float* x     = (const float*)d_in[0];  // [16384, 512]
    const float* W     = (const float*)d_in[1];  // [512, 256]
    const float* means = (const float*)d_in[2];  // [1000, 256]
    float* out = (float*)d_out;                  // [16384, 1000]
    (void)in_sizes; (void)n_in; (void)out_size;

    dim3 g1(NF / 64, NS / 128);   // (4, 128)
    k_gemm_xw<<<g1, 256>>>(x, W);
    k_score_argmax<<<NS / 128, 256>>>(means, out);
}

// round 6
// speedup vs baseline: 1.1711x; 1.1711x over previous
#include <cuda_runtime.h>
#include <cstdint>
#include <float.h>

// Problem shape (fixed by the reference)
#define NS   16384   // samples
#define DIN  512     // input dim
#define NF   256     // feature dim
#define NC   1000    // classes

// Scratch for feats = x @ W (allocation-free: device global)
__device__ __align__(16) float g_F[NS * NF];

// ---------------- f32x2 packed-FMA helpers (Blackwell) ----------------
__device__ __forceinline__ void ffma2(unsigned long long& acc,
                                      unsigned long long a,
                                      unsigned long long b) {
    asm("fma.rn.f32x2 %0, %1, %2, %0;" : "+l"(acc) : "l"(a), "l"(b));
}
__device__ __forceinline__ unsigned long long pack2(float x) {
    unsigned long long r;
    asm("mov.b64 %0, {%1, %1};" : "=l"(r) : "f"(x));
    return r;
}
__device__ __forceinline__ float2 unpack2(unsigned long long v) {
    float2 f;
    asm("mov.b64 {%0, %1}, %2;" : "=f"(f.x), "=f"(f.y) : "l"(v));
    return f;
}

// =====================================================================
// Kernel 1: F[NS,NF] = x[NS,DIN] @ W[DIN,NF]   (fp32, f32x2 FMA)
// CTA: 128 rows x 64 cols. Full W n-slice resident in smem (512x64),
// x staged in double-buffered BK=32 chunks with register prefetch.
// =====================================================================
#define K1_WS_ELEMS (512 * 64)
#define K1_AS_STRIDE 132
#define K1_AS_ELEMS (32 * K1_AS_STRIDE)
#define K1_SMEM_BYTES ((K1_WS_ELEMS + 2 * K1_AS_ELEMS) * 4)

__global__ __launch_bounds__(256) void k_gemm_xw(const float* __restrict__ x,
                                                 const float* __restrict__ W) {
    extern __shared__ float sm1[];
    float* Ws = sm1;                    // [k][n] = [512][64]
    float* As = sm1 + K1_WS_ELEMS;      // [2][32][132], k-major (transposed)

    const int t  = threadIdx.x;
    const int tx = t & 15, ty = t >> 4;
    const int m0 = blockIdx.y * 128;
    const int n0 = blockIdx.x * 64;
    const int row0 = ty * 8, col0 = tx * 4;

    // Load the full W slice once (direct copy, already [k][n]).
#pragma unroll
    for (int i = 0; i < 32; i++) {
        int f = t + i * 256;
        int k = f >> 4, nq = f & 15;
        *reinterpret_cast<float4*>(&Ws[k * 64 + nq * 4]) =
            *reinterpret_cast<const float4*>(&W[(size_t)k * NF + n0 + nq * 4]);
    }

    // Prologue: chunk 0 -> regs -> buf0
    float4 rg[4];
#pragma unroll
    for (int i = 0; i < 4; i++) {
        int f = t + i * 256;
        int row = f >> 3, kq = f & 7;
        rg[i] = *reinterpret_cast<const float4*>(&x[(size_t)(m0 + row) * DIN + kq * 4]);
    }
#pragma unroll
    for (int i = 0; i < 4; i++) {
        int f = t + i * 256;
        int row = f >> 3, kq = f & 7;
        As[(kq * 4 + 0) * K1_AS_STRIDE + row] = rg[i].x;
        As[(kq * 4 + 1) * K1_AS_STRIDE + row] = rg[i].y;
        As[(kq * 4 + 2) * K1_AS_STRIDE + row] = rg[i].z;
        As[(kq * 4 + 3) * K1_AS_STRIDE + row] = rg[i].w;
    }
    __syncthreads();

    unsigned long long acc[4][4];
#pragma unroll
    for (int p = 0; p < 4; p++)
#pragma unroll
        for (int c = 0; c < 4; c++) acc[p][c] = 0ull;

#pragma unroll 1
    for (int c = 0; c < 16; c++) {
        const float* Ac = As + (c & 1) * K1_AS_ELEMS;
        // Prefetch next chunk into registers (overlaps with compute below)
        if (c + 1 < 16) {
            int kbase = (c + 1) * 32;
#pragma unroll
            for (int i = 0; i < 4; i++) {
                int f = t + i * 256;
                int row = f >> 3, kq = f & 7;
                rg[i] = *reinterpret_cast<const float4*>(
                    &x[(size_t)(m0 + row) * DIN + kbase + kq * 4]);
            }
        }
        const float* Bp = Ws + c * 32 * 64;
#pragma unroll
        for (int k = 0; k < 32; k++) {
            ulonglong2 a01 = *reinterpret_cast<const ulonglong2*>(&Ac[k * K1_AS_STRIDE + row0]);
            ulonglong2 a23 = *reinterpret_cast<const ulonglong2*>(&Ac[k * K1_AS_STRIDE + row0 + 4]);
            float4 bv = *reinterpret_cast<const float4*>(&Bp[k * 64 + col0]);
            unsigned long long ap[4] = {a01.x, a01.y, a23.x, a23.y};
            unsigned long long bb[4] = {pack2(bv.x), pack2(bv.y), pack2(bv.z), pack2(bv.w)};
#pragma unroll
            for (int p = 0; p < 4; p++)
#pragma unroll
                for (int q = 0; q < 4; q++) ffma2(acc[p][q], ap[p], bb[q]);
        }
        if (c + 1 < 16) {
            __syncthreads();
            float* An = As + ((c + 1) & 1) * K1_AS_ELEMS;
#pragma unroll
            for (int i = 0; i < 4; i++) {
                int f = t + i * 256;
                int row = f >> 3, kq = f & 7;
                An[(kq * 4 + 0) * K1_AS_STRIDE + row] = rg[i].x;
                An[(kq * 4 + 1) * K1_AS_STRIDE + row] = rg[i].y;
                An[(kq * 4 + 2) * K1_AS_STRIDE + row] = rg[i].z;
                An[(kq * 4 + 3) * K1_AS_STRIDE + row] = rg[i].w;
            }
            __syncthreads();
        }
    }

    // Epilogue: unpack row-pairs, store to g_F
#pragma unroll
    for (int p = 0; p < 4; p++) {
        float2 c0 = unpack2(acc[p][0]);
        float2 c1 = unpack2(acc[p][1]);
        float2 c2 = unpack2(acc[p][2]);
        float2 c3 = unpack2(acc[p][3]);
        *reinterpret_cast<float4*>(&g_F[(size_t)(m0 + row0 + 2 * p) * NF + n0 + col0]) =
            make_float4(c0.x, c1.x, c2.x, c3.x);
        *reinterpret_cast<float4*>(&g_F[(size_t)(m0 + row0 + 2 * p + 1) * NF + n0 + col0]) =
            make_float4(c0.y, c1.y, c2.y, c3.y);
    }
}

// =====================================================================
// Kernel 2: S = F @ means^T, per-row argmax (first-max tie-break),
// one-hot write. Entire 128x256 F block resident in smem (loaded ONCE),
// full-K means tile per 64-class group. No per-k-chunk syncs.
// =====================================================================
#define K2_AS_STRIDE 132
#define K2_AS_ELEMS (256 * K2_AS_STRIDE)     // 33792 floats
#define K2_BS_STRIDE 68
#define K2_BS_ELEMS (256 * K2_BS_STRIDE)     // 17408 floats
#define K2_SMEM_BYTES ((K2_AS_ELEMS + K2_BS_ELEMS) * 4)   // 204800 B

__global__ __launch_bounds__(256) void k_score_argmax(const float* __restrict__ means,
                                                      float* __restrict__ out) {
    extern __shared__ float sm2[];
    float* As = sm2;                    // [k][m] = [256][132]
    float* Bs = sm2 + K2_AS_ELEMS;      // [k][c] = [256][68]
    __shared__ int sidx[128];

    const int t  = threadIdx.x;
    const int tx = t & 15, ty = t >> 4;
    const int m0 = blockIdx.x * 128;
    const int row0 = ty * 8, col0 = tx * 4;

    // Load the whole F block once, transposed to k-major.
#pragma unroll
    for (int i = 0; i < 32; i++) {
        int f = t + i * 256;
        int row = f >> 6, q = f & 63;
        float4 v = *reinterpret_cast<const float4*>(&g_F[(size_t)(m0 + row) * NF + q * 4]);
        As[(q * 4 + 0) * K2_AS_STRIDE + row] = v.x;
        As[(q * 4 + 1) * K2_AS_STRIDE + row] = v.y;
        As[(q * 4 + 2) * K2_AS_STRIDE + row] = v.z;
        As[(q * 4 + 3) * K2_AS_STRIDE + row] = v.w;
    }

    float bvrun[8];
    int   birun[8];
#pragma unroll
    for (int r = 0; r < 8; r++) { bvrun[r] = -FLT_MAX; birun[r] = 0x7FFFFFFF; }

#pragma unroll 1
    for (int ct = 0; ct < 16; ct++) {
        __syncthreads();   // previous tile's compute done (also covers As on ct=0)
        // Load means tile [64 classes][256 k] -> Bs transposed, zero-pad >= NC
        {
            int c = t >> 2, q = t & 3;
            int cls = ct * 64 + c;
#pragma unroll
            for (int kk = 0; kk < 16; kk++) {
                int kb = q * 4 + kk * 16;
                float4 v = make_float4(0.f, 0.f, 0.f, 0.f);
                if (cls < NC)
                    v = *reinterpret_cast<const float4*>(&means[(size_t)cls * NF + kb]);
                Bs[(kb + 0) * K2_BS_STRIDE + c] = v.x;
                Bs[(kb + 1) * K2_BS_STRIDE + c] = v.y;
                Bs[(kb + 2) * K2_BS_STRIDE + c] = v.z;
                Bs[(kb + 3) * K2_BS_STRIDE + c] = v.w;
            }
        }
        __syncthreads();

        unsigned long long acc[4][4];
#pragma unroll
        for (int p = 0; p < 4; p++)
#pragma unroll
            for (int c = 0; c < 4; c++) acc[p][c] = 0ull;

#pragma unroll 1
        for (int k0 = 0; k0 < NF; k0 += 16) {
#pragma unroll
            for (int kk = 0; kk < 16; kk++) {
                int k = k0 + kk;
                ulonglong2 a01 = *reinterpret_cast<const ulonglong2*>(&As[k * K2_AS_STRIDE + row0]);
                ulonglong2 a23 = *reinterpret_cast<const ulonglong2*>(&As[k * K2_AS_STRIDE + row0 + 4]);
                float4 bv = *reinterpret_cast<const float4*>(&Bs[k * K2_BS_STRIDE + col0]);
                unsigned long long ap[4] = {a01.x, a01.y, a23.x, a23.y};
                unsigned long long bb[4] = {pack2(bv.x), pack2(bv.y), pack2(bv.z), pack2(bv.w)};
#pragma unroll
                for (int p = 0; p < 4; p++)
#pragma unroll
                    for (int q = 0; q < 4; q++) ffma2(acc[p][q], ap[p], bb[q]);
            }
        }

        // Fold this tile into the running per-row best — thread-local only.
        const int cbase = ct * 64 + col0;
#pragma unroll
        for (int p = 0; p < 4; p++) {
            float2 u0 = unpack2(acc[p][0]);
            float2 u1 = unpack2(acc[p][1]);
            float2 u2 = unpack2(acc[p][2]);
            float2 u3 = unpack2(acc[p][3]);
            float s[2][4] = {{u0.x, u1.x, u2.x, u3.x},   // row 2p
                             {u0.y, u1.y, u2.y, u3.y}};  // row 2p+1
#pragma unroll
            for (int h = 0; h < 2; h++) {
                int r = 2 * p + h;
#pragma unroll
                for (int j = 0; j < 4; j++) {
                    int cls2 = cbase + j;
                    // candidates arrive in ascending class order; strict >
                    // keeps the lowest class on exact ties (torch argmin)
                    if (cls2 < NC && s[h][j] > bvrun[r]) {
                        bvrun[r] = s[h][j];
                        birun[r] = cls2;
                    }
                }
            }
        }
    }

    // Single cross-lane reduce at the end (16-lane tx group per row).
#pragma unroll
    for (int r = 0; r < 8; r++) {
        float v = bvrun[r];
        int idx = birun[r];
#pragma unroll
        for (int off = 1; off < 16; off <<= 1) {
            float ov = __shfl_xor_sync(0xffffffffu, v, off);
            int   oi = __shfl_xor_sync(0xffffffffu, idx, off);
            if (ov > v || (ov == v && oi < idx)) { v = ov; idx = oi; }
        }
        if (tx == 0) sidx[row0 + r] = idx;
    }
    __syncthreads();

    // One-hot write: zero-fill (coalesced float4) then scatter 1.0f.
    const float4 z4 = make_float4(0.f, 0.f, 0.f, 0.f);
#pragma unroll 1
    for (int r = 0; r < 128; r++) {
        if (t < 250)
            reinterpret_cast<float4*>(&out[(size_t)(m0 + r) * NC])[t] = z4;
    }
    __syncthreads();
    if (t < 128) out[(size_t)(m0 + t) * NC + sidx[t]] = 1.0f;
}

// =====================================================================
extern "C" void kernel_launch(void* const* d_in, const int* in_sizes, int n_in,
                              void* d_out, int out_size) {
    const float* x     = (const float*)d_in[0];  // [16384, 512]
    const float* W     = (const float*)d_in[1];  // [512, 256]
    const float* means = (const float*)d_in[2];  // [1000, 256]
    float* out = (float*)d_out;                  // [16384, 1000]
    (void)in_sizes; (void)n_in; (void)out_size;

    cudaFuncSetAttribute(k_gemm_xw, cudaFuncAttributeMaxDynamicSharedMemorySize,
                         K1_SMEM_BYTES);
    cudaFuncSetAttribute(k_score_argmax, cudaFuncAttributeMaxDynamicSharedMemorySize,
                         K2_SMEM_BYTES);

    dim3 g1(NF / 64, NS / 128);   // (4, 128)
    k_gemm_xw<<<g1, 256, K1_SMEM_BYTES>>>(x, W);
    k_score_argmax<<<NS / 128, 256, K2_SMEM_BYTES>>>(means, out);
}

// round 7
// speedup vs baseline: 1.1876x; 1.0141x over previous
#include <cuda_runtime.h>
#include <cstdint>
#include <float.h>

// Problem shape (fixed by the reference)
#define NS   16384   // samples
#define DIN  512     // input dim
#define NF   256     // feature dim
#define NC   1000    // classes

// ---------------- smem layout (floats), phases overlap ----------------
#define AS1_STRIDE 132
#define AS1_ELEMS  (32 * AS1_STRIDE)        // 4224   (x chunk, k-major)
#define WS_ELEMS   (32 * 256)               // 8192   (W chunk, [k][n])
#define AS2_STRIDE 132
#define AS2_ELEMS  (256 * AS2_STRIDE)       // 33792  (F block, k-major)
#define BS_STRIDE  132
#define BS_ELEMS   (128 * BS_STRIDE)        // 16896  (means chunk, k-major)
#define SMEM_FLOATS (AS2_ELEMS + BS_ELEMS)  // 50688
#define SMEM_BYTES  (SMEM_FLOATS * 4)       // 202752
static_assert(2 * AS1_ELEMS + 2 * WS_ELEMS <= SMEM_FLOATS, "phase1 fits");

// ---------------- f32x2 packed-FMA helpers (Blackwell) ----------------
__device__ __forceinline__ void ffma2(unsigned long long& acc,
                                      unsigned long long a,
                                      unsigned long long b) {
    asm("fma.rn.f32x2 %0, %1, %2, %0;" : "+l"(acc) : "l"(a), "l"(b));
}
__device__ __forceinline__ unsigned long long pack2(float x) {
    unsigned long long r;
    asm("mov.b64 %0, {%1, %1};" : "=l"(r) : "f"(x));
    return r;
}
__device__ __forceinline__ float2 unpack2(unsigned long long v) {
    float2 f;
    asm("mov.b64 {%0, %1}, %2;" : "=f"(f.x), "=f"(f.y) : "l"(v));
    return f;
}

// =====================================================================
// Fused kernel: per CTA of 512 threads over 128 sample rows:
//   Phase 1: F = x_blk[128,512] @ W[512,256]  (8x8 per-thread reg tile)
//   Phase 2: S = F @ means^T, running argmax, one-hot write
// =====================================================================
__global__ __launch_bounds__(512, 1) void k_fused(const float* __restrict__ x,
                                                  const float* __restrict__ W,
                                                  const float* __restrict__ means,
                                                  float* __restrict__ out) {
    extern __shared__ float sm[];
    __shared__ int sidx[128];

    const int t   = threadIdx.x;
    const int tx  = t & 31, ty = t >> 5;
    const int row0 = ty * 8;      // 16 warps x 8 rows = 128
    const int col0 = tx * 4;
    const int m0 = blockIdx.x * 128;

    // ================= Phase 1: F = x_blk @ W =================
    float* As1 = sm;                    // [2][32][132] k-major x chunk
    float* Ws  = sm + 2 * AS1_ELEMS;    // [2][32][256] W chunk

    float4 xr[2], wr[4];
    // ---- prologue: chunk 0 ----
#pragma unroll
    for (int i = 0; i < 2; i++) {
        int f = t + i * 512;
        int row = f >> 3, kq = f & 7;
        xr[i] = *reinterpret_cast<const float4*>(&x[(size_t)(m0 + row) * DIN + kq * 4]);
    }
#pragma unroll
    for (int i = 0; i < 4; i++) {
        int f = t + i * 512;
        int k = f >> 6, nq = f & 63;
        wr[i] = *reinterpret_cast<const float4*>(&W[(size_t)k * NF + nq * 4]);
    }
#pragma unroll
    for (int i = 0; i < 2; i++) {
        int f = t + i * 512;
        int row = f >> 3, kq = f & 7;
        As1[(kq * 4 + 0) * AS1_STRIDE + row] = xr[i].x;
        As1[(kq * 4 + 1) * AS1_STRIDE + row] = xr[i].y;
        As1[(kq * 4 + 2) * AS1_STRIDE + row] = xr[i].z;
        As1[(kq * 4 + 3) * AS1_STRIDE + row] = xr[i].w;
    }
#pragma unroll
    for (int i = 0; i < 4; i++) {
        int f = t + i * 512;
        int k = f >> 6, nq = f & 63;
        *reinterpret_cast<float4*>(&Ws[k * 256 + nq * 4]) = wr[i];
    }
    __syncthreads();

    unsigned long long acc1[4][8];
#pragma unroll
    for (int p = 0; p < 4; p++)
#pragma unroll
        for (int c = 0; c < 8; c++) acc1[p][c] = 0ull;

#pragma unroll 1
    for (int ch = 0; ch < 16; ch++) {
        const float* Ac = As1 + (ch & 1) * AS1_ELEMS;
        const float* Wc = Ws + (ch & 1) * WS_ELEMS;
        // register-prefetch next chunk (hides LDG under compute)
        if (ch + 1 < 16) {
            int kb = (ch + 1) * 32;
#pragma unroll
            for (int i = 0; i < 2; i++) {
                int f = t + i * 512;
                int row = f >> 3, kq = f & 7;
                xr[i] = *reinterpret_cast<const float4*>(
                    &x[(size_t)(m0 + row) * DIN + kb + kq * 4]);
            }
#pragma unroll
            for (int i = 0; i < 4; i++) {
                int f = t + i * 512;
                int k = f >> 6, nq = f & 63;
                wr[i] = *reinterpret_cast<const float4*>(
                    &W[(size_t)(kb + k) * NF + nq * 4]);
            }
        }
#pragma unroll 4
        for (int k = 0; k < 32; k++) {
            const float* Ap = Ac + k * AS1_STRIDE + row0;
            ulonglong2 a01 = *reinterpret_cast<const ulonglong2*>(Ap);
            ulonglong2 a23 = *reinterpret_cast<const ulonglong2*>(Ap + 4);
            float4 blo = *reinterpret_cast<const float4*>(&Wc[k * 256 + col0]);
            float4 bhi = *reinterpret_cast<const float4*>(&Wc[k * 256 + 128 + col0]);
            unsigned long long ap[4] = {a01.x, a01.y, a23.x, a23.y};
            unsigned long long bb[8] = {pack2(blo.x), pack2(blo.y), pack2(blo.z), pack2(blo.w),
                                        pack2(bhi.x), pack2(bhi.y), pack2(bhi.z), pack2(bhi.w)};
#pragma unroll
            for (int p = 0; p < 4; p++)
#pragma unroll
                for (int c = 0; c < 8; c++) ffma2(acc1[p][c], ap[p], bb[c]);
        }
        if (ch + 1 < 16) {
            float* An = As1 + ((ch + 1) & 1) * AS1_ELEMS;
            float* Wn = Ws + ((ch + 1) & 1) * WS_ELEMS;
#pragma unroll
            for (int i = 0; i < 2; i++) {
                int f = t + i * 512;
                int row = f >> 3, kq = f & 7;
                An[(kq * 4 + 0) * AS1_STRIDE + row] = xr[i].x;
                An[(kq * 4 + 1) * AS1_STRIDE + row] = xr[i].y;
                An[(kq * 4 + 2) * AS1_STRIDE + row] = xr[i].z;
                An[(kq * 4 + 3) * AS1_STRIDE + row] = xr[i].w;
            }
#pragma unroll
            for (int i = 0; i < 4; i++) {
                int f = t + i * 512;
                int k = f >> 6, nq = f & 63;
                *reinterpret_cast<float4*>(&Wn[k * 256 + nq * 4]) = wr[i];
            }
            __syncthreads();
        }
    }
    __syncthreads();   // all phase-1 smem reads done before As2 overwrites

    // ======= Transition: F (regs) -> As2 (k-major smem) =======
    float* As2 = sm;                 // [256][132]
    float* Bs  = sm + AS2_ELEMS;     // [128][132]
#pragma unroll
    for (int c = 0; c < 8; c++) {
        int kcol = (c < 4) ? (col0 + c) : (128 + col0 + (c - 4));
#pragma unroll
        for (int p = 0; p < 4; p++) {
            float2 u = unpack2(acc1[p][c]);
            *reinterpret_cast<float2*>(&As2[kcol * AS2_STRIDE + row0 + 2 * p]) = u;
        }
    }
    // barrier before first Bs store / As2 reads happens at top of chunk loop

    // ================= Phase 2: scores + argmax =================
    float bv[8];
    int   bi[8];
#pragma unroll
    for (int r = 0; r < 8; r++) { bv[r] = -FLT_MAX; bi[r] = 0x7FFFFFFF; }

    const int c_ld = t & 127, q_ld = t >> 7;   // means-chunk loader mapping
    float4 br[8];
    auto load_bs = [&](int ch) {
        int ct2 = ch >> 1, half2 = ch & 1;
        int cls = ct2 * 128 + c_ld;
        const float* mp = means + (size_t)cls * NF + half2 * 128 + q_ld * 4;
        bool ok = (cls < NC);
#pragma unroll
        for (int j = 0; j < 8; j++)
            br[j] = ok ? *reinterpret_cast<const float4*>(mp + j * 16)
                       : make_float4(0.f, 0.f, 0.f, 0.f);
    };
    load_bs(0);

    unsigned long long acc2[4][4];

#pragma unroll 1
    for (int ch = 0; ch < 16; ch++) {          // ch = class_tile*2 + k_half
        const int ct = ch >> 1, half = ch & 1;
        __syncthreads();                        // Bs free / As2 visible
#pragma unroll
        for (int j = 0; j < 8; j++) {
            int kb = q_ld * 4 + j * 16;
            Bs[(kb + 0) * BS_STRIDE + c_ld] = br[j].x;
            Bs[(kb + 1) * BS_STRIDE + c_ld] = br[j].y;
            Bs[(kb + 2) * BS_STRIDE + c_ld] = br[j].z;
            Bs[(kb + 3) * BS_STRIDE + c_ld] = br[j].w;
        }
        __syncthreads();
        if (ch + 1 < 16) load_bs(ch + 1);       // prefetch hides under k-loop

        if (half == 0) {
#pragma unroll
            for (int p = 0; p < 4; p++)
#pragma unroll
                for (int c = 0; c < 4; c++) acc2[p][c] = 0ull;
        }

        const float* Abase = As2 + half * 128 * AS2_STRIDE + row0;
#pragma unroll 8
        for (int kk = 0; kk < 128; kk++) {
            const float* Ap = Abase + kk * AS2_STRIDE;
            ulonglong2 a01 = *reinterpret_cast<const ulonglong2*>(Ap);
            ulonglong2 a23 = *reinterpret_cast<const ulonglong2*>(Ap + 4);
            float4 b4 = *reinterpret_cast<const float4*>(&Bs[kk * BS_STRIDE + col0]);
            unsigned long long ap[4] = {a01.x, a01.y, a23.x, a23.y};
            unsigned long long bb[4] = {pack2(b4.x), pack2(b4.y), pack2(b4.z), pack2(b4.w)};
#pragma unroll
            for (int p = 0; p < 4; p++)
#pragma unroll
                for (int c = 0; c < 4; c++) ffma2(acc2[p][c], ap[p], bb[c]);
        }

        if (half == 1) {
            const int cbase = ct * 128 + col0;
#pragma unroll
            for (int p = 0; p < 4; p++) {
                float2 u0 = unpack2(acc2[p][0]);
                float2 u1 = unpack2(acc2[p][1]);
                float2 u2 = unpack2(acc2[p][2]);
                float2 u3 = unpack2(acc2[p][3]);
                float s[2][4] = {{u0.x, u1.x, u2.x, u3.x},   // row 2p
                                 {u0.y, u1.y, u2.y, u3.y}};  // row 2p+1
#pragma unroll
                for (int h = 0; h < 2; h++) {
                    int r = 2 * p + h;
#pragma unroll
                    for (int j = 0; j < 4; j++) {
                        int cls2 = cbase + j;
                        // ascending class order + strict > == first-max tie-break
                        if (cls2 < NC && s[h][j] > bv[r]) {
                            bv[r] = s[h][j];
                            bi[r] = cls2;
                        }
                    }
                }
            }
        }
    }

    // Full-warp (val,idx) reduce per row; lowest class wins ties.
#pragma unroll
    for (int r = 0; r < 8; r++) {
        float v = bv[r];
        int idx = bi[r];
#pragma unroll
        for (int off = 1; off < 32; off <<= 1) {
            float ov = __shfl_xor_sync(0xffffffffu, v, off);
            int   oi = __shfl_xor_sync(0xffffffffu, idx, off);
            if (ov > v || (ov == v && oi < idx)) { v = ov; idx = oi; }
        }
        if (tx == 0) sidx[row0 + r] = idx;
    }
    __syncthreads();

    // One-hot: coalesced float4 zero-fill, then scatter 1.0f.
    const float4 z4 = make_float4(0.f, 0.f, 0.f, 0.f);
#pragma unroll 1
    for (int i = t; i < 128 * 256; i += 512) {
        int row = i >> 8, c = i & 255;
        if (c < 250)
            *reinterpret_cast<float4*>(&out[(size_t)(m0 + row) * NC + c * 4]) = z4;
    }
    __syncthreads();
    if (t < 128) out[(size_t)(m0 + t) * NC + sidx[t]] = 1.0f;
}

// =====================================================================
extern "C" void kernel_launch(void* const* d_in, const int* in_sizes, int n_in,
                              void* d_out, int out_size) {
    const float* x     = (const float*)d_in[0];  // [16384, 512]
    const float* W     = (const float*)d_in[1];  // [512, 256]
    const float* means = (const float*)d_in[2];  // [1000, 256]
    float* out = (float*)d_out;                  // [16384, 1000]
    (void)in_sizes; (void)n_in; (void)out_size;

    cudaFuncSetAttribute(k_fused, cudaFuncAttributeMaxDynamicSharedMemorySize,
                         SMEM_BYTES);
    k_fused<<<NS / 128, 512, SMEM_BYTES>>>(x, W, means, out);
}

// round 8
// speedup vs baseline: 1.3643x; 1.1487x over previous
#include <cuda_runtime.h>
#include <cstdint>
#include <float.h>

// Problem shape (fixed by the reference)
#define NS   16384   // samples
#define DIN  512     // input dim
#define NF   256     // feature dim
#define NC   1000    // classes
#define NCP  1024    // padded classes

// meansT [k][class] fp32, zero-padded to 1024 classes (one-time transpose)
__device__ __align__(16) float g_mT[NF * NCP];

// ---------------- smem layout (floats), phases overlap ----------------
#define AS1_STRIDE 132
#define AS1_ELEMS  (32 * AS1_STRIDE)        // x chunk, k-major, x2 buffers
#define WS_ELEMS   (32 * 256)               // W chunk [k][n], x2 buffers
#define AS2_STRIDE 132
#define AS2_ELEMS  (256 * AS2_STRIDE)       // F block, k-major
#define BS_STRIDE  132
#define BS_ELEMS   (64 * BS_STRIDE)         // meansT chunk [k][c], x2 buffers
#define SMEM_FLOATS (AS2_ELEMS + 2 * BS_ELEMS)   // 33792 + 16896 = 50688
#define SMEM_BYTES  (SMEM_FLOATS * 4)            // 202752
static_assert(2 * AS1_ELEMS + 2 * WS_ELEMS <= SMEM_FLOATS, "phase1 fits");

// ---------------- f32x2 packed-FMA helpers (Blackwell) ----------------
__device__ __forceinline__ void ffma2(unsigned long long& acc,
                                      unsigned long long a,
                                      unsigned long long b) {
    asm("fma.rn.f32x2 %0, %1, %2, %0;" : "+l"(acc) : "l"(a), "l"(b));
}
__device__ __forceinline__ unsigned long long pack2(float x) {
    unsigned long long r;
    asm("mov.b64 %0, {%1, %1};" : "=l"(r) : "f"(x));
    return r;
}
__device__ __forceinline__ float2 unpack2(unsigned long long v) {
    float2 f;
    asm("mov.b64 {%0, %1}, %2;" : "=f"(f.x), "=f"(f.y) : "l"(v));
    return f;
}
__device__ __forceinline__ unsigned smem_u32(const void* p) {
    return (unsigned)__cvta_generic_to_shared(p);
}
__device__ __forceinline__ void cp16(unsigned dst, const float* src) {
    asm volatile("cp.async.ca.shared.global [%0], [%1], 16;" :: "r"(dst), "l"(src));
}
#define CP_COMMIT() asm volatile("cp.async.commit_group;")
#define CP_WAIT0()  asm volatile("cp.async.wait_group 0;")

// =====================================================================
// One-time: meansT[k][c] = means[c][k], zero-pad c >= NC. Tiled transpose.
// =====================================================================
__global__ void k_prep(const float* __restrict__ means) {
    __shared__ float tile[32][33];
    const int c0 = blockIdx.x * 32, k0 = blockIdx.y * 32;
    const int tx = threadIdx.x, ty = threadIdx.y;   // 32 x 8
#pragma unroll
    for (int i = 0; i < 32; i += 8) {
        int c = c0 + ty + i;
        tile[ty + i][tx] = (c < NC) ? means[(size_t)c * NF + k0 + tx] : 0.f;
    }
    __syncthreads();
#pragma unroll
    for (int i = 0; i < 32; i += 8)
        g_mT[(size_t)(k0 + ty + i) * NCP + c0 + tx] = tile[tx][ty + i];
}

// =====================================================================
// Fused kernel: 512 threads per CTA over 128 sample rows.
//   Phase 1: F = x_blk[128,512] @ W[512,256]   (8x8 reg tile, f32x2)
//   Phase 2: S = F @ meansT, running argmax, one-hot write
// All B-side staging via cp.async double-buffering (zero reg residency).
// =====================================================================
__global__ __launch_bounds__(512, 1) void k_fused(const float* __restrict__ x,
                                                  const float* __restrict__ W,
                                                  float* __restrict__ out) {
    extern __shared__ float sm[];
    __shared__ int sidx[128];

    const int t   = threadIdx.x;
    const int tx  = t & 31, ty = t >> 5;
    const int row0 = ty * 8;      // 16 warps x 8 rows = 128
    const int col0 = tx * 4;
    const int m0 = blockIdx.x * 128;

    // ================= Phase 1: F = x_blk @ W =================
    float* As1 = sm;                    // [2][32][132] k-major x chunk
    float* Ws  = sm + 2 * AS1_ELEMS;    // [2][32][256] W chunk

    auto issueW = [&](int ch, int buf) {
        float* dst = Ws + buf * WS_ELEMS;
        const float* src = W + (size_t)ch * 32 * NF;
#pragma unroll
        for (int i = 0; i < 4; i++) {
            int q = t + i * 512;               // 0..2047 quads
            int kk = q >> 6, nq = q & 63;
            cp16(smem_u32(dst + kk * 256 + nq * 4), src + (size_t)kk * NF + nq * 4);
        }
        CP_COMMIT();
    };

    float4 xr[2];
    auto loadX = [&](int ch) {
#pragma unroll
        for (int i = 0; i < 2; i++) {
            int f = t + i * 512;
            int row = f >> 3, kq = f & 7;
            xr[i] = *reinterpret_cast<const float4*>(
                &x[(size_t)(m0 + row) * DIN + ch * 32 + kq * 4]);
        }
    };
    auto storeX = [&](int buf) {
        float* A = As1 + buf * AS1_ELEMS;
#pragma unroll
        for (int i = 0; i < 2; i++) {
            int f = t + i * 512;
            int row = f >> 3, kq = f & 7;
            A[(kq * 4 + 0) * AS1_STRIDE + row] = xr[i].x;
            A[(kq * 4 + 1) * AS1_STRIDE + row] = xr[i].y;
            A[(kq * 4 + 2) * AS1_STRIDE + row] = xr[i].z;
            A[(kq * 4 + 3) * AS1_STRIDE + row] = xr[i].w;
        }
    };

    // prologue: chunk 0
    issueW(0, 0);
    loadX(0);
    storeX(0);
    CP_WAIT0();
    __syncthreads();

    unsigned long long acc1[4][8];
#pragma unroll
    for (int p = 0; p < 4; p++)
#pragma unroll
        for (int c = 0; c < 8; c++) acc1[p][c] = 0ull;

#pragma unroll 1
    for (int ch = 0; ch < 16; ch++) {
        if (ch + 1 < 16) {
            issueW(ch + 1, (ch + 1) & 1);   // copy overlaps compute below
            loadX(ch + 1);                  // x prefetch (8 regs only)
        }
        const float* Ac = As1 + (ch & 1) * AS1_ELEMS;
        const float* Wc = Ws + (ch & 1) * WS_ELEMS;
#pragma unroll 4
        for (int k = 0; k < 32; k++) {
            const float* Ap = Ac + k * AS1_STRIDE + row0;
            ulonglong2 a01 = *reinterpret_cast<const ulonglong2*>(Ap);
            ulonglong2 a23 = *reinterpret_cast<const ulonglong2*>(Ap + 4);
            float4 blo = *reinterpret_cast<const float4*>(&Wc[k * 256 + col0]);
            float4 bhi = *reinterpret_cast<const float4*>(&Wc[k * 256 + 128 + col0]);
            unsigned long long ap[4] = {a01.x, a01.y, a23.x, a23.y};
            unsigned long long bb[8] = {pack2(blo.x), pack2(blo.y), pack2(blo.z), pack2(blo.w),
                                        pack2(bhi.x), pack2(bhi.y), pack2(bhi.z), pack2(bhi.w)};
#pragma unroll
            for (int p = 0; p < 4; p++)
#pragma unroll
                for (int c = 0; c < 8; c++) ffma2(acc1[p][c], ap[p], bb[c]);
        }
        if (ch + 1 < 16) {
            storeX((ch + 1) & 1);   // writes buf not in use this iter
            CP_WAIT0();
            __syncthreads();        // single barrier per chunk
        }
    }
    __syncthreads();   // all phase-1 smem reads done before As2 overwrite

    // ======= Transition: F (regs) -> As2 (k-major smem) =======
    float* As2 = sm;                 // [256][132]
    float* Bs  = sm + AS2_ELEMS;     // [2][64][132]
#pragma unroll
    for (int c = 0; c < 8; c++) {
        int kcol = (c < 4) ? (col0 + c) : (128 + col0 + (c - 4));
#pragma unroll
        for (int p = 0; p < 4; p++) {
            float2 u = unpack2(acc1[p][c]);
            *reinterpret_cast<float2*>(&As2[kcol * AS2_STRIDE + row0 + 2 * p]) = u;
        }
    }

    // ================= Phase 2: scores + argmax =================
    auto issueB = [&](int ch, int buf) {
        int ct = ch >> 2, kq = ch & 3;   // class tile 128, k-chunk 64
        float* dst = Bs + buf * BS_ELEMS;
        const float* src = g_mT + (size_t)(kq * 64) * NCP + ct * 128;
#pragma unroll
        for (int i = 0; i < 4; i++) {
            int q = t + i * 512;               // 0..2047 quads
            int kk = q >> 5, cq = q & 31;
            cp16(smem_u32(dst + kk * BS_STRIDE + cq * 4), src + (size_t)kk * NCP + cq * 4);
        }
        CP_COMMIT();
    };

    issueB(0, 0);
    CP_WAIT0();
    __syncthreads();    // As2 visible + B(0) landed

    float bv[8];
    int   bi[8];
#pragma unroll
    for (int r = 0; r < 8; r++) { bv[r] = -FLT_MAX; bi[r] = 0x7FFFFFFF; }

    unsigned long long acc2[4][4];

#pragma unroll 1
    for (int ch = 0; ch < 32; ch++) {          // ch = class_tile*4 + k_chunk
        const int ct = ch >> 2, kq = ch & 3;
        if (ch + 1 < 32) issueB(ch + 1, (ch + 1) & 1);   // overlaps compute

        if (kq == 0) {
#pragma unroll
            for (int p = 0; p < 4; p++)
#pragma unroll
                for (int c = 0; c < 4; c++) acc2[p][c] = 0ull;
        }

        const float* Ab = As2 + kq * 64 * AS2_STRIDE + row0;
        const float* Bb = Bs + (ch & 1) * BS_ELEMS;
#pragma unroll 8
        for (int kk = 0; kk < 64; kk++) {
            const float* Ap = Ab + kk * AS2_STRIDE;
            ulonglong2 a01 = *reinterpret_cast<const ulonglong2*>(Ap);
            ulonglong2 a23 = *reinterpret_cast<const ulonglong2*>(Ap + 4);
            float4 b4 = *reinterpret_cast<const float4*>(&Bb[kk * BS_STRIDE + col0]);
            unsigned long long ap[4] = {a01.x, a01.y, a23.x, a23.y};
            unsigned long long bb[4] = {pack2(b4.x), pack2(b4.y), pack2(b4.z), pack2(b4.w)};
#pragma unroll
            for (int p = 0; p < 4; p++)
#pragma unroll
                for (int c = 0; c < 4; c++) ffma2(acc2[p][c], ap[p], bb[c]);
        }

        if (kq == 3) {
            const int cbase = ct * 128 + col0;
#pragma unroll
            for (int p = 0; p < 4; p++) {
                float2 u0 = unpack2(acc2[p][0]);
                float2 u1 = unpack2(acc2[p][1]);
                float2 u2 = unpack2(acc2[p][2]);
                float2 u3 = unpack2(acc2[p][3]);
                float s[2][4] = {{u0.x, u1.x, u2.x, u3.x},   // row 2p
                                 {u0.y, u1.y, u2.y, u3.y}};  // row 2p+1
#pragma unroll
                for (int h = 0; h < 2; h++) {
                    int r = 2 * p + h;
#pragma unroll
                    for (int j = 0; j < 4; j++) {
                        int cls2 = cbase + j;
                        // ascending class order + strict > == first-max tie-break
                        if (cls2 < NC && s[h][j] > bv[r]) {
                            bv[r] = s[h][j];
                            bi[r] = cls2;
                        }
                    }
                }
            }
        }
        if (ch + 1 < 32) {
            CP_WAIT0();
            __syncthreads();        // single barrier per chunk
        }
    }

    // Full-warp (val,idx) reduce per row; lowest class wins ties.
#pragma unroll
    for (int r = 0; r < 8; r++) {
        float v = bv[r];
        int idx = bi[r];
#pragma unroll
        for (int off = 1; off < 32; off <<= 1) {
            float ov = __shfl_xor_sync(0xffffffffu, v, off);
            int   oi = __shfl_xor_sync(0xffffffffu, idx, off);
            if (ov > v || (ov == v && oi < idx)) { v = ov; idx = oi; }
        }
        if (tx == 0) sidx[row0 + r] = idx;
    }
    __syncthreads();

    // One-hot: coalesced float4 zero-fill, then scatter 1.0f.
    const float4 z4 = make_float4(0.f, 0.f, 0.f, 0.f);
#pragma unroll 1
    for (int i = t; i < 128 * 256; i += 512) {
        int row = i >> 8, c = i & 255;
        if (c < 250)
            *reinterpret_cast<float4*>(&out[(size_t)(m0 + row) * NC + c * 4]) = z4;
    }
    __syncthreads();
    if (t < 128) out[(size_t)(m0 + t) * NC + sidx[t]] = 1.0f;
}

// =====================================================================
extern "C" void kernel_launch(void* const* d_in, const int* in_sizes, int n_in,
                              void* d_out, int out_size) {
    const float* x     = (const float*)d_in[0];  // [16384, 512]
    const float* W     = (const float*)d_in[1];  // [512, 256]
    const float* means = (const float*)d_in[2];  // [1000, 256]
    float* out = (float*)d_out;                  // [16384, 1000]
    (void)in_sizes; (void)n_in; (void)out_size;

    cudaFuncSetAttribute(k_fused, cudaFuncAttributeMaxDynamicSharedMemorySize,
                         SMEM_BYTES);
    k_prep<<<dim3(NCP / 32, NF / 32), dim3(32, 8)>>>(means);
    k_fused<<<NS / 128, 512, SMEM_BYTES>>>(x, W, out);
}